// round 15
// baseline (speedup 1.0000x reference)
#include <cuda_runtime.h>
#include <math.h>

#ifndef M_PI
#define M_PI 3.14159265358979323846
#endif

#define NBT 48
#define NC  64
#define NX  128
#define NY  128
#define NB  4
#define TIN 12
#define TOUT 4
#define UD  3
#define NDEPTH 4

typedef unsigned long long u64;

__device__ __forceinline__ u64 f2fma(u64 a, u64 b, u64 c) {
    u64 r; asm("fma.rn.f32x2 %0,%1,%2,%3;" : "=l"(r) : "l"(a), "l"(b), "l"(c)); return r;
}
__device__ __forceinline__ u64 f2sub(u64 a, u64 b) {
    u64 r; asm("sub.rn.f32x2 %0,%1,%2;" : "=l"(r) : "l"(a), "l"(b)); return r;
}
__device__ __forceinline__ u64 f2pack(float lo, float hi) {
    u64 r; asm("mov.b64 %0,{%1,%2};" : "=l"(r) : "f"(lo), "f"(hi)); return r;
}
__device__ __forceinline__ u64 f2dup(float v) { return f2pack(v, v); }
__device__ __forceinline__ float2 f2unpack(u64 a) {
    float2 r; asm("mov.b64 {%0,%1},%2;" : "=f"(r.x), "=f"(r.y) : "l"(a)); return r;
}
__device__ __forceinline__ u64 f2neg(u64 a) { return a ^ 0x8000000080000000ULL; }

// ---------------- scratch ---------------------------------------------------
__device__ float g_X [NBT*NC*NX*NY];
__device__ float g_Yf[NBT*NC*NX*32];
__device__ float g_Zr[NBT*NC*512];
__device__ float g_Zi[NBT*NC*512];
__device__ float g_Or[NBT*NC*512];
__device__ float g_Oi[NBT*NC*512];
__device__ float g_Xi[NBT*NC*NX*32];
__device__ float g_Wfy2[64*32*2];
__device__ float g_Wfx[128*32*2];
__device__ float g_Wix[32*128*2];
__device__ float g_Cy [16*128];
__device__ float g_Sy [16*128];

// ---------------- table init ------------------------------------------------
__global__ void init_tables_kernel() {
    int tid = blockIdx.x * blockDim.x + threadIdx.x;
    if (tid < 64*32) {
        int yp = tid >> 5, k = tid & 31;
        int kk = k & 15;
        for (int j = 0; j < 2; j++) {
            int y = 2*yp + j;
            double th = (2.0 * M_PI / 128.0) * (double)((kk * y) & 127);
            g_Wfy2[tid*2 + j] = (k < 16) ? (float)cos(th) : (float)(-sin(th));
        }
    }
    if (tid < 128*32) {
        int x = tid >> 5, m = tid & 31;
        int kx = (m < 16) ? m : (96 + m);
        double th = (2.0 * M_PI / 128.0) * (double)((kx * x) & 127);
        g_Wfx[2*tid]   = (float)cos(th);
        g_Wfx[2*tid+1] = (float)(-sin(th));
    }
    if (tid < 32*128) {
        int m = tid >> 7, x = tid & 127;
        int kx = (m < 16) ? m : (96 + m);
        double th = (2.0 * M_PI / 128.0) * (double)((kx * x) & 127);
        g_Wix[2*tid]   = (float)(cos(th) / 128.0);
        g_Wix[2*tid+1] = (float)(sin(th) / 128.0);
    }
    if (tid < 16*128) {
        int k = tid >> 7, y = tid & 127;
        if (k == 0) { g_Cy[tid] = 1.0f/128.0f; g_Sy[tid] = 0.0f; }
        else {
            double th = (2.0 * M_PI / 128.0) * (double)((k * y) & 127);
            g_Cy[tid] = (float)( 2.0 * cos(th) / 128.0);
            g_Sy[tid] = (float)(-2.0 * sin(th) / 128.0);
        }
    }
}

// ---------------- fused lift (3->64) + forward y-DFT -----------------------
__global__ __launch_bounds__(256) void lift_fwdy_kernel(
    const float* __restrict__ in, const float* __restrict__ Pw,
    const float* __restrict__ Pb)
{
    __shared__ float sL[8192];
    __shared__ float sPw[192], sPb[64], sIn[384];
    int tid = threadIdx.x;
    int x = blockIdx.x, bt = blockIdx.y;

    if (tid < 192) sPw[tid] = Pw[tid];
    if (tid < 64)  sPb[tid] = Pb[tid];
    if (tid < 128) {
#pragma unroll
        for (int u = 0; u < 3; u++)
            sIn[u*128 + tid] = in[((size_t)bt*3 + u)*16384 + x*128 + tid];
    }
    __syncthreads();

    for (int i = tid; i < 2048; i += 256) {
        int c = i >> 5, y4 = (i & 31) * 4;
        float b  = sPb[c], w0 = sPw[c*3], w1 = sPw[c*3+1], w2 = sPw[c*3+2];
        float4 r;
        r.x = b + w0*sIn[y4]   + w1*sIn[128+y4]   + w2*sIn[256+y4];
        r.y = b + w0*sIn[y4+1] + w1*sIn[128+y4+1] + w2*sIn[256+y4+1];
        r.z = b + w0*sIn[y4+2] + w1*sIn[128+y4+2] + w2*sIn[256+y4+2];
        r.w = b + w0*sIn[y4+3] + w1*sIn[128+y4+3] + w2*sIn[256+y4+3];
        *(float4*)(sL + c*128 + y4) = r;
        *(float4*)(g_X + (((size_t)bt*64 + c)*128 + x)*128 + y4) = r;
    }
    __syncthreads();

    int warp = tid >> 5, lane = tid & 31;
    const u64* w2 = (const u64*)g_Wfy2;
    int ob = warp * 8;
    u64 acc[8];
#pragma unroll
    for (int r = 0; r < 8; r++) acc[r] = 0ULL;
#pragma unroll 4
    for (int yp = 0; yp < 64; yp++) {
        u64 w = __ldg(w2 + yp*32 + lane);
#pragma unroll
        for (int r = 0; r < 8; r++) {
            u64 v2 = *(const u64*)(sL + (ob + r)*128 + 2*yp);
            acc[r] = f2fma(v2, w, acc[r]);
        }
    }
#pragma unroll
    for (int r = 0; r < 8; r++) {
        float2 p = f2unpack(acc[r]);
        g_Yf[(((size_t)bt*64 + ob + r)*128 + x)*32 + lane] = p.x + p.y;
    }
}

// ---------------- forward DFT over x (R6/R13 version, 128 threads) ---------
__global__ __launch_bounds__(128) void fwd_x_kernel() {
    __shared__ float sY0[4096], sY1[4096];
    int tid = threadIdx.x;
    const float* src = g_Yf + (size_t)blockIdx.x * 8192;
    for (int i = tid; i < 4096; i += 128) { sY0[i] = src[i]; sY1[i] = src[4096 + i]; }
    __syncthreads();
    int m   = tid >> 2;
    int ky0 = (tid & 3) * 4;
    const float2* wtab = (const float2*)g_Wfx;
    u64 rA[2][2], rB[2][2], ii[2][2];
#pragma unroll
    for (int f = 0; f < 2; f++)
#pragma unroll
        for (int p = 0; p < 2; p++) { rA[f][p] = 0ULL; rB[f][p] = 0ULL; ii[f][p] = 0ULL; }
#pragma unroll 2
    for (int x = 0; x < 128; x++) {
        float2 w = __ldg(wtab + x*32 + m);
        u64 wr2 = f2dup(w.x), wi2 = f2dup(w.y);
        u64 a00 = *(const u64*)(sY0 + x*32 + ky0);
        u64 b00 = *(const u64*)(sY0 + x*32 + 16 + ky0);
        u64 a01 = *(const u64*)(sY0 + x*32 + ky0 + 2);
        u64 b01 = *(const u64*)(sY0 + x*32 + 18 + ky0);
        u64 a10 = *(const u64*)(sY1 + x*32 + ky0);
        u64 b10 = *(const u64*)(sY1 + x*32 + 16 + ky0);
        u64 a11 = *(const u64*)(sY1 + x*32 + ky0 + 2);
        u64 b11 = *(const u64*)(sY1 + x*32 + 18 + ky0);
        rA[0][0] = f2fma(a00, wr2, rA[0][0]);  rB[0][0] = f2fma(b00, wi2, rB[0][0]);
        ii[0][0] = f2fma(a00, wi2, ii[0][0]);  ii[0][0] = f2fma(b00, wr2, ii[0][0]);
        rA[0][1] = f2fma(a01, wr2, rA[0][1]);  rB[0][1] = f2fma(b01, wi2, rB[0][1]);
        ii[0][1] = f2fma(a01, wi2, ii[0][1]);  ii[0][1] = f2fma(b01, wr2, ii[0][1]);
        rA[1][0] = f2fma(a10, wr2, rA[1][0]);  rB[1][0] = f2fma(b10, wi2, rB[1][0]);
        ii[1][0] = f2fma(a10, wi2, ii[1][0]);  ii[1][0] = f2fma(b10, wr2, ii[1][0]);
        rA[1][1] = f2fma(a11, wr2, rA[1][1]);  rB[1][1] = f2fma(b11, wi2, rB[1][1]);
        ii[1][1] = f2fma(a11, wi2, ii[1][1]);  ii[1][1] = f2fma(b11, wr2, ii[1][1]);
    }
#pragma unroll
    for (int f = 0; f < 2; f++) {
        size_t base = ((size_t)(blockIdx.x*2 + f))*512 + m*16 + ky0;
        *(u64*)(g_Zr + base)     = f2sub(rA[f][0], rB[f][0]);
        *(u64*)(g_Zr + base + 2) = f2sub(rA[f][1], rB[f][1]);
        *(u64*)(g_Zi + base)     = ii[f][0];
        *(u64*)(g_Zi + base + 2) = ii[f][1];
    }
}

// ---------------- per-mode channel mix (R9 4bt x 4o version) ---------------
__global__ __launch_bounds__(128) void mode_mix_kernel(
    const float* __restrict__ w1r, const float* __restrict__ w1i,
    const float* __restrict__ w2r, const float* __restrict__ w2i)
{
    int mp    = blockIdx.x * 128 + threadIdx.x;
    int mode0 = mp * 2;
    int half  = mode0 >> 8;
    int ml    = mode0 & 255;
    const float* Wr = half ? w2r : w1r;
    const float* Wi = half ? w2i : w1i;
    int bt0 = blockIdx.y * 4, o0 = blockIdx.z * 4;
    u64 aR[4][4], aI[4][4];
#pragma unroll
    for (int b = 0; b < 4; b++)
#pragma unroll
        for (int o = 0; o < 4; o++) { aR[b][o] = 0ULL; aI[b][o] = 0ULL; }

    for (int i = 0; i < 64; i++) {
        u64 zr[4], zi[4];
#pragma unroll
        for (int b = 0; b < 4; b++) {
            size_t zb = ((size_t)(bt0 + b)*64 + i)*512 + mode0;
            zr[b] = *(const u64*)(g_Zr + zb);
            zi[b] = *(const u64*)(g_Zi + zb);
        }
#pragma unroll
        for (int o = 0; o < 4; o++) {
            size_t wb = ((size_t)i*64 + (o0 + o))*256 + ml;
            u64 wr2  = *(const u64*)(Wr + wb);
            u64 wi2  = *(const u64*)(Wi + wb);
            u64 wi2n = f2neg(wi2);
#pragma unroll
            for (int b = 0; b < 4; b++) {
                aR[b][o] = f2fma(zr[b], wr2,  aR[b][o]);
                aR[b][o] = f2fma(zi[b], wi2n, aR[b][o]);
                aI[b][o] = f2fma(zr[b], wi2,  aI[b][o]);
                aI[b][o] = f2fma(zi[b], wr2,  aI[b][o]);
            }
        }
    }
#pragma unroll
    for (int b = 0; b < 4; b++)
#pragma unroll
        for (int o = 0; o < 4; o++) {
            size_t ob = ((size_t)(bt0 + b)*64 + (o0 + o))*512 + mode0;
            *(u64*)(g_Or + ob) = aR[b][o];
            *(u64*)(g_Oi + ob) = aI[b][o];
        }
}

// ---------------- inverse DFT over x ---------------------------------------
__global__ __launch_bounds__(256) void inv_x_kernel() {
    __shared__ float sOr[512], sOi[512];
    int tid = threadIdx.x;
    const float* srcr = g_Or + (size_t)blockIdx.x * 512;
    const float* srci = g_Oi + (size_t)blockIdx.x * 512;
    for (int i = tid; i < 512; i += 256) { sOr[i] = srcr[i]; sOi[i] = srci[i]; }
    __syncthreads();
    int x  = tid >> 1;
    int kb = (tid & 1) * 8;
    u64 arA[4], arB[4], ai[4];
#pragma unroll
    for (int j = 0; j < 4; j++) { arA[j] = 0ULL; arB[j] = 0ULL; ai[j] = 0ULL; }
#pragma unroll 4
    for (int m = 0; m < 32; m++) {
        float2 w = *(const float2*)(g_Wix + (m*128 + x)*2);
        u64 wr2 = f2dup(w.x), wi2 = f2dup(w.y);
#pragma unroll
        for (int j = 0; j < 4; j++) {
            u64 pr = *(const u64*)(sOr + m*16 + kb + 2*j);
            u64 pi = *(const u64*)(sOi + m*16 + kb + 2*j);
            arA[j] = f2fma(pr, wr2, arA[j]);
            arB[j] = f2fma(pi, wi2, arB[j]);
            ai[j]  = f2fma(pr, wi2, ai[j]);
            ai[j]  = f2fma(pi, wr2, ai[j]);
        }
    }
    float* dst = g_Xi + ((size_t)blockIdx.x * 128 + x) * 32;
#pragma unroll
    for (int j = 0; j < 4; j++) {
        *(u64*)(dst + kb + 2*j)      = f2sub(arA[j], arB[j]);
        *(u64*)(dst + 16 + kb + 2*j) = ai[j];
    }
}

// ---------------- fused tail v6: R13 + float4 weight loads in phase 2 ------
__global__ __launch_bounds__(256, 3) void fused_tail_kernel(
    const float* __restrict__ gctxd,
    const float* __restrict__ llw,
    const float* __restrict__ llb,
    const float* __restrict__ lng, const float* __restrict__ lnb,
    int write_yf)
{
    extern __shared__ float sm[];
    float* sXV  = sm;
    float* sLL  = sm + 8192;
    float* sXi  = sm + 12288;
    float* sCtx = sm + 8192;      // alias after phase 2
    float* sCyH = sm + 16384;
    float* sSyH = sm + 17408;
    float* sPS  = sm + 16384;     // alias after phase 2
    float* sPQ  = sm + 16640;
    float* sMu  = sm + 16896;
    float* sRs  = sm + 17024;
    float* sLNg = sm + 18432;
    float* sLNb = sm + 18496;
    float* sLLb = sm + 18560;

    int tid = threadIdx.x;
    int x   = blockIdx.x;
    int bt  = blockIdx.y;

    float cxf = x * 0.5f - 0.25f;
    int ix0 = (int)floorf(cxf);
    float wx1 = cxf - (float)ix0, wx0 = 1.0f - wx1;
    int cx0 = min(63, max(0, ix0));
    int cx1 = min(63, max(0, ix0 + 1));

    // phase 1: loads (vectorized)
    for (int i = tid; i < 2048; i += 256) {
        int c = i >> 5, y4 = (i & 31) * 4;
        *(float4*)(sXV + c*128 + y4) =
            *(const float4*)(g_X + (((size_t)bt*64 + c)*128 + x)*128 + y4);
    }
    for (int i = tid; i < 1024; i += 256)
        *(float4*)(sLL + i*4) = *(const float4*)(llw + i*4);
    for (int i = tid; i < 512; i += 256) {
        int o = i >> 3, k4 = (i & 7) * 4;
        *(float4*)(sXi + o*32 + k4) =
            *(const float4*)(g_Xi + (((size_t)bt*64 + o)*128 + x)*32 + k4);
    }
    for (int i = tid; i < 1024; i += 256) {
        int k = i >> 6, yy = i & 63;
        sCyH[i] = g_Cy[k*128 + yy];
        sSyH[i] = g_Sy[k*128 + yy];
    }
    if (tid < 64) { sLNg[tid] = lng[tid]; sLNb[tid] = lnb[tid]; sLLb[tid] = llb[tid]; }
    __syncthreads();

    // phase 2: V[o][y] = LL @ X + inv-y(Xi)
    int o0  = (tid >> 5) * 8;
    int tx4 = (tid & 31) * 4;
    int yh  = tx4 & 63;
    u64 sgn = (tx4 >= 64) ? 0x8000000080000000ULL : 0ULL;
    u64 acc0[8], acc1[8];
#pragma unroll
    for (int oo = 0; oo < 8; oo++) { acc0[oo] = 0ULL; acc1[oo] = 0ULL; }

    // c-loop unrolled by 4; weights fetched as float4 per (oo, c-quad)
    for (int c4 = 0; c4 < 64; c4 += 4) {
        ulonglong2 xv0 = *(const ulonglong2*)(sXV + (c4+0)*128 + tx4);
        ulonglong2 xv1 = *(const ulonglong2*)(sXV + (c4+1)*128 + tx4);
        ulonglong2 xv2 = *(const ulonglong2*)(sXV + (c4+2)*128 + tx4);
        ulonglong2 xv3 = *(const ulonglong2*)(sXV + (c4+3)*128 + tx4);
#pragma unroll
        for (int oo = 0; oo < 8; oo++) {
            float4 w4 = *(const float4*)(sLL + (o0 + oo)*64 + c4);
            u64 d0 = f2dup(w4.x), d1 = f2dup(w4.y), d2 = f2dup(w4.z), d3 = f2dup(w4.w);
            acc0[oo] = f2fma(xv0.x, d0, acc0[oo]);
            acc1[oo] = f2fma(xv0.y, d0, acc1[oo]);
            acc0[oo] = f2fma(xv1.x, d1, acc0[oo]);
            acc1[oo] = f2fma(xv1.y, d1, acc1[oo]);
            acc0[oo] = f2fma(xv2.x, d2, acc0[oo]);
            acc1[oo] = f2fma(xv2.y, d2, acc1[oo]);
            acc0[oo] = f2fma(xv3.x, d3, acc0[oo]);
            acc1[oo] = f2fma(xv3.y, d3, acc1[oo]);
        }
    }
#pragma unroll
    for (int ky = 0; ky < 16; ky++) {
        ulonglong2 cy = *(const ulonglong2*)(sCyH + ky*64 + yh);
        ulonglong2 sy = *(const ulonglong2*)(sSyH + ky*64 + yh);
        if (ky & 1) {
            cy.x ^= sgn; cy.y ^= sgn; sy.x ^= sgn; sy.y ^= sgn;
        }
#pragma unroll
        for (int oo = 0; oo < 8; oo++) {
            u64 xr2 = f2dup(sXi[(o0 + oo)*32 + ky]);
            u64 xi2 = f2dup(sXi[(o0 + oo)*32 + 16 + ky]);
            acc0[oo] = f2fma(xr2, cy.x, acc0[oo]);
            acc0[oo] = f2fma(xi2, sy.x, acc0[oo]);
            acc1[oo] = f2fma(xr2, cy.y, acc1[oo]);
            acc1[oo] = f2fma(xi2, sy.y, acc1[oo]);
        }
    }
    __syncthreads();
#pragma unroll
    for (int oo = 0; oo < 8; oo++) {
        float b = sLLb[o0 + oo];
        float2 v0 = f2unpack(acc0[oo]);
        float2 v1 = f2unpack(acc1[oo]);
        *(float4*)(sXV + (o0 + oo)*128 + tx4) =
            make_float4(v0.x + b, v0.y + b, v1.x + b, v1.y + b);
    }
    for (int i = tid; i < 2048; i += 256) {
        int o = i >> 5, q = i & 31;
        int j = q >> 4, c4 = (q & 15) * 4;
        int cx = j ? cx1 : cx0;
        *(float4*)(sCtx + o*128 + j*64 + c4) =
            *(const float4*)(gctxd + ((size_t)bt*64 + o)*4096 + cx*64 + c4);
    }
    __syncthreads();

    // phase 3: LN stats
    {
        int yy = tid & 127, oh = tid >> 7;
        float s = 0.f, ss = 0.f;
        int ob = oh * 32;
        for (int o = ob; o < ob + 32; o++) {
            float v = sXV[o*128 + yy];
            s += v; ss += v*v;
        }
        sPS[tid] = s; sPQ[tid] = ss;
    }
    __syncthreads();
    if (tid < 128) {
        float s = sPS[tid] + sPS[128 + tid];
        float q = sPQ[tid] + sPQ[128 + tid];
        float mu = s * (1.0f/64.0f);
        float var = q * (1.0f/64.0f) - mu*mu;
        sMu[tid] = mu;
        sRs[tid] = rsqrtf(var + 1e-5f);
    }
    __syncthreads();

    // phase 4 (vectorized): per-thread fixed y-quad; o = j*8 + warp
    int y0 = (tid & 31) * 4;
    float muq[4], rsq[4], wyA[4], wyB[4];
    int cyA[4], cyB[4];
#pragma unroll
    for (int e = 0; e < 4; e++) {
        int y = y0 + e;
        muq[e] = sMu[y]; rsq[e] = sRs[y];
        float cyf = y * 0.5f - 0.25f;
        int iy0 = (int)floorf(cyf);
        float wy1 = cyf - (float)iy0;
        wyB[e] = wy1; wyA[e] = 1.0f - wy1;
        cyA[e] = min(63, max(0, iy0));
        cyB[e] = min(63, max(0, iy0 + 1));
    }
    int warpo = tid >> 5;
    for (int j = 0; j < 8; j++) {
        int o = j*8 + warpo;
        float4 v4 = *(const float4*)(sXV + o*128 + y0);
        float g0_ = sLNg[o], b0_ = sLNb[o];
        const float* cr = sCtx + o*128;
        float r[4] = {v4.x, v4.y, v4.z, v4.w};
#pragma unroll
        for (int e = 0; e < 4; e++) {
            float v = (r[e] - muq[e]) * rsq[e] * g0_ + b0_;
            v = 0.5f * v * (1.0f + erff(v * 0.70710678118654752440f));
            float g = wx0 * (wyA[e] * cr[cyA[e]] + wyB[e] * cr[cyB[e]])
                    + wx1 * (wyA[e] * cr[64 + cyA[e]] + wyB[e] * cr[64 + cyB[e]]);
            r[e] = v + g;
        }
        float4 out4 = make_float4(r[0], r[1], r[2], r[3]);
        *(float4*)(g_X + (((size_t)bt*64 + o)*128 + x)*128 + y0) = out4;
        *(float4*)(sXV + o*128 + y0) = out4;
    }

    // phase 5: fused y-DFT -> g_Yf
    if (write_yf) {
        __syncthreads();
        int warp = tid >> 5, lane = tid & 31;
        const u64* w2 = (const u64*)g_Wfy2;
        int ob = warp * 8;
        u64 acc[8];
#pragma unroll
        for (int r = 0; r < 8; r++) acc[r] = 0ULL;
#pragma unroll 4
        for (int yp = 0; yp < 64; yp++) {
            u64 w = __ldg(w2 + yp*32 + lane);
#pragma unroll
            for (int r = 0; r < 8; r++) {
                u64 v2 = *(const u64*)(sXV + (ob + r)*128 + 2*yp);
                acc[r] = f2fma(v2, w, acc[r]);
            }
        }
#pragma unroll
        for (int r = 0; r < 8; r++) {
            float2 p = f2unpack(acc[r]);
            g_Yf[(((size_t)bt*64 + ob + r)*128 + x)*32 + lane] = p.x + p.y;
        }
    }
}

// ---------------- temporal aggregation + projection ------------------------
__global__ __launch_bounds__(256) void head_kernel(
    const float* __restrict__ Wtw, const float* __restrict__ Wtb,
    const float* __restrict__ Qw,  const float* __restrict__ Qb,
    float* __restrict__ out)
{
    __shared__ float sWt[48], sWtb[4], sQ[192], sQb[3], sQS[3];
    int tid = threadIdx.x;
    if (tid < 48)  sWt[tid]  = Wtw[tid];
    if (tid < 4)   sWtb[tid] = Wtb[tid];
    if (tid < 192) sQ[tid]   = Qw[tid];
    if (tid < 3)   sQb[tid]  = Qb[tid];
    __syncthreads();
    if (tid < 3) {
        float s = 0.f;
        for (int c = 0; c < 64; c++) s += sQ[tid*64 + c];
        sQS[tid] = s;
    }
    __syncthreads();
    int idx = blockIdx.x * 256 + tid;
    int b = idx >> 14, xy = idx & 16383;
    float acc[TOUT][UD] = {};
    for (int c = 0; c < 64; c++) {
        float xv[TIN];
#pragma unroll
        for (int t = 0; t < TIN; t++)
            xv[t] = g_X[(((size_t)(b*TIN + t))*64 + c)*16384 + xy];
        float tt[TOUT];
#pragma unroll
        for (int o = 0; o < TOUT; o++) {
            float s = 0.f;
#pragma unroll
            for (int t = 0; t < TIN; t++) s += sWt[o*TIN + t] * xv[t];
            tt[o] = s;
        }
#pragma unroll
        for (int u = 0; u < UD; u++) {
            float q = sQ[u*64 + c];
#pragma unroll
            for (int o = 0; o < TOUT; o++) acc[o][u] += q * tt[o];
        }
    }
#pragma unroll
    for (int o = 0; o < TOUT; o++)
#pragma unroll
        for (int u = 0; u < UD; u++)
            out[(((size_t)b*TOUT + o)*UD + u)*16384 + xy] =
                acc[o][u] + sWtb[o]*sQS[u] + sQb[u];
}

// ---------------- launcher --------------------------------------------------
extern "C" void kernel_launch(void* const* d_in, const int* in_sizes, int n_in,
                              void* d_out, int out_size)
{
    const float* input = (const float*)d_in[0];
    const float* gctx  = (const float*)d_in[1];
    const float* P_w   = (const float*)d_in[2];
    const float* P_b   = (const float*)d_in[3];
    const float* Q_w   = (const float*)d_in[4];
    const float* Q_b   = (const float*)d_in[5];
    const float* Wt_w  = (const float*)d_in[6];
    const float* Wt_b  = (const float*)d_in[7];
    const float* w1r   = (const float*)d_in[8];
    const float* w1i   = (const float*)d_in[9];
    const float* w2r   = (const float*)d_in[10];
    const float* w2i   = (const float*)d_in[11];
    const float* ll_w  = (const float*)d_in[12];
    const float* ll_b  = (const float*)d_in[13];
    const float* ln_g  = (const float*)d_in[14];
    const float* ln_b  = (const float*)d_in[15];
    float* out = (float*)d_out;

    const int FUSED_SMEM = 18624 * 4;   // 74496 bytes -> 3 blocks/SM
    cudaFuncSetAttribute(fused_tail_kernel,
                         cudaFuncAttributeMaxDynamicSharedMemorySize, FUSED_SMEM);

    init_tables_kernel<<<16, 256>>>();
    dim3 gl(128, NBT);
    lift_fwdy_kernel<<<gl, 256>>>(input, P_w, P_b);

    const size_t SPEC_D = (size_t)64*64*16*16;
    for (int d = 0; d < NDEPTH; d++) {
        fwd_x_kernel<<<1536, 128>>>();
        dim3 g3(2, 12, 16);
        mode_mix_kernel<<<g3, 128>>>(w1r + d*SPEC_D, w1i + d*SPEC_D,
                                     w2r + d*SPEC_D, w2i + d*SPEC_D);
        inv_x_kernel<<<NBT*NC, 256>>>();
        dim3 g5(128, NBT);
        fused_tail_kernel<<<g5, 256, FUSED_SMEM>>>(
            gctx + (size_t)d*NBT*64*4096,
            ll_w + (size_t)d*4096, ll_b + d*64, ln_g + d*64, ln_b + d*64,
            (d < NDEPTH-1) ? 1 : 0);
    }
    head_kernel<<<256, 256>>>(Wt_w, Wt_b, Q_w, Q_b, out);
}

// round 16
// speedup vs baseline: 1.0458x; 1.0458x over previous
#include <cuda_runtime.h>
#include <math.h>

#ifndef M_PI
#define M_PI 3.14159265358979323846
#endif

#define NBT 48
#define NC  64
#define NX  128
#define NY  128
#define NB  4
#define TIN 12
#define TOUT 4
#define UD  3
#define NDEPTH 4

typedef unsigned long long u64;

__device__ __forceinline__ u64 f2fma(u64 a, u64 b, u64 c) {
    u64 r; asm("fma.rn.f32x2 %0,%1,%2,%3;" : "=l"(r) : "l"(a), "l"(b), "l"(c)); return r;
}
__device__ __forceinline__ u64 f2sub(u64 a, u64 b) {
    u64 r; asm("sub.rn.f32x2 %0,%1,%2;" : "=l"(r) : "l"(a), "l"(b)); return r;
}
__device__ __forceinline__ u64 f2pack(float lo, float hi) {
    u64 r; asm("mov.b64 %0,{%1,%2};" : "=l"(r) : "f"(lo), "f"(hi)); return r;
}
__device__ __forceinline__ u64 f2dup(float v) { return f2pack(v, v); }
__device__ __forceinline__ float2 f2unpack(u64 a) {
    float2 r; asm("mov.b64 {%0,%1},%2;" : "=f"(r.x), "=f"(r.y) : "l"(a)); return r;
}
__device__ __forceinline__ u64 f2neg(u64 a) { return a ^ 0x8000000080000000ULL; }

// ---------------- scratch ---------------------------------------------------
__device__ float g_X [NBT*NC*NX*NY];
__device__ float g_Yf[NBT*NC*NX*32];
__device__ float g_Zr[NBT*NC*512];
__device__ float g_Zi[NBT*NC*512];
__device__ float g_Or[NBT*NC*512];
__device__ float g_Oi[NBT*NC*512];
__device__ float g_Xi[NBT*NC*NX*32];
__device__ float g_Wfy2[64*32*2];
__device__ float g_Wfx[128*32*2];
__device__ float g_Wix[32*128*2];
__device__ float g_Cy [16*128];
__device__ float g_Sy [16*128];

// ---------------- table init ------------------------------------------------
__global__ void init_tables_kernel() {
    int tid = blockIdx.x * blockDim.x + threadIdx.x;
    if (tid < 64*32) {
        int yp = tid >> 5, k = tid & 31;
        int kk = k & 15;
        for (int j = 0; j < 2; j++) {
            int y = 2*yp + j;
            double th = (2.0 * M_PI / 128.0) * (double)((kk * y) & 127);
            g_Wfy2[tid*2 + j] = (k < 16) ? (float)cos(th) : (float)(-sin(th));
        }
    }
    if (tid < 128*32) {
        int x = tid >> 5, m = tid & 31;
        int kx = (m < 16) ? m : (96 + m);
        double th = (2.0 * M_PI / 128.0) * (double)((kx * x) & 127);
        g_Wfx[2*tid]   = (float)cos(th);
        g_Wfx[2*tid+1] = (float)(-sin(th));
    }
    if (tid < 32*128) {
        int m = tid >> 7, x = tid & 127;
        int kx = (m < 16) ? m : (96 + m);
        double th = (2.0 * M_PI / 128.0) * (double)((kx * x) & 127);
        g_Wix[2*tid]   = (float)(cos(th) / 128.0);
        g_Wix[2*tid+1] = (float)(sin(th) / 128.0);
    }
    if (tid < 16*128) {
        int k = tid >> 7, y = tid & 127;
        if (k == 0) { g_Cy[tid] = 1.0f/128.0f; g_Sy[tid] = 0.0f; }
        else {
            double th = (2.0 * M_PI / 128.0) * (double)((k * y) & 127);
            g_Cy[tid] = (float)( 2.0 * cos(th) / 128.0);
            g_Sy[tid] = (float)(-2.0 * sin(th) / 128.0);
        }
    }
}

// ---------------- fused lift (3->64) + forward y-DFT -----------------------
__global__ __launch_bounds__(256) void lift_fwdy_kernel(
    const float* __restrict__ in, const float* __restrict__ Pw,
    const float* __restrict__ Pb)
{
    __shared__ float sL[8192];
    __shared__ float sPw[192], sPb[64], sIn[384];
    int tid = threadIdx.x;
    int x = blockIdx.x, bt = blockIdx.y;

    if (tid < 192) sPw[tid] = Pw[tid];
    if (tid < 64)  sPb[tid] = Pb[tid];
    if (tid < 128) {
#pragma unroll
        for (int u = 0; u < 3; u++)
            sIn[u*128 + tid] = in[((size_t)bt*3 + u)*16384 + x*128 + tid];
    }
    __syncthreads();

    for (int i = tid; i < 2048; i += 256) {
        int c = i >> 5, y4 = (i & 31) * 4;
        float b  = sPb[c], w0 = sPw[c*3], w1 = sPw[c*3+1], w2 = sPw[c*3+2];
        float4 r;
        r.x = b + w0*sIn[y4]   + w1*sIn[128+y4]   + w2*sIn[256+y4];
        r.y = b + w0*sIn[y4+1] + w1*sIn[128+y4+1] + w2*sIn[256+y4+1];
        r.z = b + w0*sIn[y4+2] + w1*sIn[128+y4+2] + w2*sIn[256+y4+2];
        r.w = b + w0*sIn[y4+3] + w1*sIn[128+y4+3] + w2*sIn[256+y4+3];
        *(float4*)(sL + c*128 + y4) = r;
        *(float4*)(g_X + (((size_t)bt*64 + c)*128 + x)*128 + y4) = r;
    }
    __syncthreads();

    int warp = tid >> 5, lane = tid & 31;
    const u64* w2 = (const u64*)g_Wfy2;
    int ob = warp * 8;
    u64 acc[8];
#pragma unroll
    for (int r = 0; r < 8; r++) acc[r] = 0ULL;
#pragma unroll 4
    for (int yp = 0; yp < 64; yp++) {
        u64 w = __ldg(w2 + yp*32 + lane);
#pragma unroll
        for (int r = 0; r < 8; r++) {
            u64 v2 = *(const u64*)(sL + (ob + r)*128 + 2*yp);
            acc[r] = f2fma(v2, w, acc[r]);
        }
    }
#pragma unroll
    for (int r = 0; r < 8; r++) {
        float2 p = f2unpack(acc[r]);
        g_Yf[(((size_t)bt*64 + ob + r)*128 + x)*32 + lane] = p.x + p.y;
    }
}

// ---------------- forward DFT over x (R6/R13 version, 128 threads) ---------
__global__ __launch_bounds__(128) void fwd_x_kernel() {
    __shared__ float sY0[4096], sY1[4096];
    int tid = threadIdx.x;
    const float* src = g_Yf + (size_t)blockIdx.x * 8192;
    for (int i = tid; i < 4096; i += 128) { sY0[i] = src[i]; sY1[i] = src[4096 + i]; }
    __syncthreads();
    int m   = tid >> 2;
    int ky0 = (tid & 3) * 4;
    const float2* wtab = (const float2*)g_Wfx;
    u64 rA[2][2], rB[2][2], ii[2][2];
#pragma unroll
    for (int f = 0; f < 2; f++)
#pragma unroll
        for (int p = 0; p < 2; p++) { rA[f][p] = 0ULL; rB[f][p] = 0ULL; ii[f][p] = 0ULL; }
#pragma unroll 2
    for (int x = 0; x < 128; x++) {
        float2 w = __ldg(wtab + x*32 + m);
        u64 wr2 = f2dup(w.x), wi2 = f2dup(w.y);
        u64 a00 = *(const u64*)(sY0 + x*32 + ky0);
        u64 b00 = *(const u64*)(sY0 + x*32 + 16 + ky0);
        u64 a01 = *(const u64*)(sY0 + x*32 + ky0 + 2);
        u64 b01 = *(const u64*)(sY0 + x*32 + 18 + ky0);
        u64 a10 = *(const u64*)(sY1 + x*32 + ky0);
        u64 b10 = *(const u64*)(sY1 + x*32 + 16 + ky0);
        u64 a11 = *(const u64*)(sY1 + x*32 + ky0 + 2);
        u64 b11 = *(const u64*)(sY1 + x*32 + 18 + ky0);
        rA[0][0] = f2fma(a00, wr2, rA[0][0]);  rB[0][0] = f2fma(b00, wi2, rB[0][0]);
        ii[0][0] = f2fma(a00, wi2, ii[0][0]);  ii[0][0] = f2fma(b00, wr2, ii[0][0]);
        rA[0][1] = f2fma(a01, wr2, rA[0][1]);  rB[0][1] = f2fma(b01, wi2, rB[0][1]);
        ii[0][1] = f2fma(a01, wi2, ii[0][1]);  ii[0][1] = f2fma(b01, wr2, ii[0][1]);
        rA[1][0] = f2fma(a10, wr2, rA[1][0]);  rB[1][0] = f2fma(b10, wi2, rB[1][0]);
        ii[1][0] = f2fma(a10, wi2, ii[1][0]);  ii[1][0] = f2fma(b10, wr2, ii[1][0]);
        rA[1][1] = f2fma(a11, wr2, rA[1][1]);  rB[1][1] = f2fma(b11, wi2, rB[1][1]);
        ii[1][1] = f2fma(a11, wi2, ii[1][1]);  ii[1][1] = f2fma(b11, wr2, ii[1][1]);
    }
#pragma unroll
    for (int f = 0; f < 2; f++) {
        size_t base = ((size_t)(blockIdx.x*2 + f))*512 + m*16 + ky0;
        *(u64*)(g_Zr + base)     = f2sub(rA[f][0], rB[f][0]);
        *(u64*)(g_Zr + base + 2) = f2sub(rA[f][1], rB[f][1]);
        *(u64*)(g_Zi + base)     = ii[f][0];
        *(u64*)(g_Zi + base + 2) = ii[f][1];
    }
}

// ---------------- per-mode channel mix (R9 4bt x 4o version) ---------------
__global__ __launch_bounds__(128) void mode_mix_kernel(
    const float* __restrict__ w1r, const float* __restrict__ w1i,
    const float* __restrict__ w2r, const float* __restrict__ w2i)
{
    int mp    = blockIdx.x * 128 + threadIdx.x;
    int mode0 = mp * 2;
    int half  = mode0 >> 8;
    int ml    = mode0 & 255;
    const float* Wr = half ? w2r : w1r;
    const float* Wi = half ? w2i : w1i;
    int bt0 = blockIdx.y * 4, o0 = blockIdx.z * 4;
    u64 aR[4][4], aI[4][4];
#pragma unroll
    for (int b = 0; b < 4; b++)
#pragma unroll
        for (int o = 0; o < 4; o++) { aR[b][o] = 0ULL; aI[b][o] = 0ULL; }

    for (int i = 0; i < 64; i++) {
        u64 zr[4], zi[4];
#pragma unroll
        for (int b = 0; b < 4; b++) {
            size_t zb = ((size_t)(bt0 + b)*64 + i)*512 + mode0;
            zr[b] = *(const u64*)(g_Zr + zb);
            zi[b] = *(const u64*)(g_Zi + zb);
        }
#pragma unroll
        for (int o = 0; o < 4; o++) {
            size_t wb = ((size_t)i*64 + (o0 + o))*256 + ml;
            u64 wr2  = *(const u64*)(Wr + wb);
            u64 wi2  = *(const u64*)(Wi + wb);
            u64 wi2n = f2neg(wi2);
#pragma unroll
            for (int b = 0; b < 4; b++) {
                aR[b][o] = f2fma(zr[b], wr2,  aR[b][o]);
                aR[b][o] = f2fma(zi[b], wi2n, aR[b][o]);
                aI[b][o] = f2fma(zr[b], wi2,  aI[b][o]);
                aI[b][o] = f2fma(zi[b], wr2,  aI[b][o]);
            }
        }
    }
#pragma unroll
    for (int b = 0; b < 4; b++)
#pragma unroll
        for (int o = 0; o < 4; o++) {
            size_t ob = ((size_t)(bt0 + b)*64 + (o0 + o))*512 + mode0;
            *(u64*)(g_Or + ob) = aR[b][o];
            *(u64*)(g_Oi + ob) = aI[b][o];
        }
}

// ---------------- inverse DFT over x ---------------------------------------
__global__ __launch_bounds__(256) void inv_x_kernel() {
    __shared__ float sOr[512], sOi[512];
    int tid = threadIdx.x;
    const float* srcr = g_Or + (size_t)blockIdx.x * 512;
    const float* srci = g_Oi + (size_t)blockIdx.x * 512;
    for (int i = tid; i < 512; i += 256) { sOr[i] = srcr[i]; sOi[i] = srci[i]; }
    __syncthreads();
    int x  = tid >> 1;
    int kb = (tid & 1) * 8;
    u64 arA[4], arB[4], ai[4];
#pragma unroll
    for (int j = 0; j < 4; j++) { arA[j] = 0ULL; arB[j] = 0ULL; ai[j] = 0ULL; }
#pragma unroll 4
    for (int m = 0; m < 32; m++) {
        float2 w = *(const float2*)(g_Wix + (m*128 + x)*2);
        u64 wr2 = f2dup(w.x), wi2 = f2dup(w.y);
#pragma unroll
        for (int j = 0; j < 4; j++) {
            u64 pr = *(const u64*)(sOr + m*16 + kb + 2*j);
            u64 pi = *(const u64*)(sOi + m*16 + kb + 2*j);
            arA[j] = f2fma(pr, wr2, arA[j]);
            arB[j] = f2fma(pi, wi2, arB[j]);
            ai[j]  = f2fma(pr, wi2, ai[j]);
            ai[j]  = f2fma(pi, wr2, ai[j]);
        }
    }
    float* dst = g_Xi + ((size_t)blockIdx.x * 128 + x) * 32;
#pragma unroll
    for (int j = 0; j < 4; j++) {
        *(u64*)(dst + kb + 2*j)      = f2sub(arA[j], arB[j]);
        *(u64*)(dst + 16 + kb + 2*j) = ai[j];
    }
}

// ---------------- fused tail v7: phase-2 o-pair operands -------------------
// 256 threads; dyn smem 18624 floats = 74496 B; grid (128, 48); 3 blocks/SM
// layout (floats):
//   sXV   [0,8192)
//   region2 [8192,16384): sLLP u64[64*33] @8192 (4224f) ;
//                         sXiP u64[32*33] @12416 (2112f)  -> sCtx after ph2
//   sCyH  [16384,17408) -> stats after ph2 ; sSyH [17408,18432)
//   sLNg [18432..] sLNb sLLb
__global__ __launch_bounds__(256, 3) void fused_tail_kernel(
    const float* __restrict__ gctxd,
    const float* __restrict__ llw,
    const float* __restrict__ llb,
    const float* __restrict__ lng, const float* __restrict__ lnb,
    int write_yf)
{
    extern __shared__ float sm[];
    float* sXV  = sm;
    u64*   sLLP = (u64*)(sm + 8192);    // [c*33 + p], p = o/2
    u64*   sXiP = (u64*)(sm + 12416);   // [k*33 + p]
    float* sCtx = sm + 8192;            // alias after phase 2
    float* sCyH = sm + 16384;
    float* sSyH = sm + 17408;
    float* sPS  = sm + 16384;           // alias after phase 2
    float* sPQ  = sm + 16640;
    float* sMu  = sm + 16896;
    float* sRs  = sm + 17024;
    float* sLNg = sm + 18432;
    float* sLNb = sm + 18496;
    float* sLLb = sm + 18560;

    int tid = threadIdx.x;
    int x   = blockIdx.x;
    int bt  = blockIdx.y;

    float cxf = x * 0.5f - 0.25f;
    int ix0 = (int)floorf(cxf);
    float wx1 = cxf - (float)ix0, wx0 = 1.0f - wx1;
    int cx0 = min(63, max(0, ix0));
    int cx1 = min(63, max(0, ix0 + 1));

    // phase 1: loads
    for (int i = tid; i < 2048; i += 256) {
        int c = i >> 5, y4 = (i & 31) * 4;
        *(float4*)(sXV + c*128 + y4) =
            *(const float4*)(g_X + (((size_t)bt*64 + c)*128 + x)*128 + y4);
    }
    // weight pair table: sLLP[c*33+p] = {llw[2p][c], llw[2p+1][c]}
    for (int i = tid; i < 2048; i += 256) {
        int c = i & 63, pp = i >> 6;
        sLLP[c*33 + pp] = f2pack(llw[(2*pp)*64 + c], llw[(2*pp+1)*64 + c]);
    }
    // Xi pair table: sXiP[k*33+p] = {Xi[2p][k], Xi[2p+1][k]}
    {
        const float* xb = g_Xi + (((size_t)bt*64)*128 + x)*32;
        for (int i = tid; i < 1024; i += 256) {
            int k = i & 31, pp = i >> 5;
            float lo = xb[(size_t)(2*pp)*4096 + k];
            float hi = xb[(size_t)(2*pp+1)*4096 + k];
            sXiP[k*33 + pp] = f2pack(lo, hi);
        }
    }
    for (int i = tid; i < 1024; i += 256) {
        int k = i >> 6, yy = i & 63;
        sCyH[i] = g_Cy[k*128 + yy];
        sSyH[i] = g_Sy[k*128 + yy];
    }
    if (tid < 64) { sLNg[tid] = lng[tid]; sLNb[tid] = lnb[tid]; sLLb[tid] = llb[tid]; }
    __syncthreads();

    // phase 2: V[o][y] = LL @ X + inv-y(Xi) ; pairs over o
    int o0  = (tid >> 5) * 8;
    int p0  = (tid >> 5) * 4;           // pair base = o0/2
    int tx4 = (tid & 31) * 4;
    int yh  = tx4 & 63;
    u64 sgn = (tx4 >= 64) ? 0x8000000080000000ULL : 0ULL;
    u64 accP[4][4];                     // [o-pair][y-elem]
#pragma unroll
    for (int p = 0; p < 4; p++)
#pragma unroll
        for (int e = 0; e < 4; e++) accP[p][e] = 0ULL;

#pragma unroll 2
    for (int c = 0; c < 64; c++) {
        float4 xq = *(const float4*)(sXV + c*128 + tx4);
        u64 xd0 = f2dup(xq.x), xd1 = f2dup(xq.y), xd2 = f2dup(xq.z), xd3 = f2dup(xq.w);
        const u64* wrow = sLLP + c*33 + p0;
#pragma unroll
        for (int p = 0; p < 4; p++) {
            u64 wp = wrow[p];
            accP[p][0] = f2fma(xd0, wp, accP[p][0]);
            accP[p][1] = f2fma(xd1, wp, accP[p][1]);
            accP[p][2] = f2fma(xd2, wp, accP[p][2]);
            accP[p][3] = f2fma(xd3, wp, accP[p][3]);
        }
    }
#pragma unroll
    for (int ky = 0; ky < 16; ky++) {
        float4 cq = *(const float4*)(sCyH + ky*64 + yh);
        float4 sq = *(const float4*)(sSyH + ky*64 + yh);
        u64 cd[4] = {f2dup(cq.x), f2dup(cq.y), f2dup(cq.z), f2dup(cq.w)};
        u64 sd[4] = {f2dup(sq.x), f2dup(sq.y), f2dup(sq.z), f2dup(sq.w)};
        if (ky & 1) {
#pragma unroll
            for (int e = 0; e < 4; e++) { cd[e] ^= sgn; sd[e] ^= sgn; }
        }
        const u64* xrrow = sXiP + ky*33 + p0;
        const u64* xirow = sXiP + (16 + ky)*33 + p0;
#pragma unroll
        for (int p = 0; p < 4; p++) {
            u64 xr = xrrow[p];
            u64 xi = xirow[p];
            accP[p][0] = f2fma(xr, cd[0], accP[p][0]);
            accP[p][0] = f2fma(xi, sd[0], accP[p][0]);
            accP[p][1] = f2fma(xr, cd[1], accP[p][1]);
            accP[p][1] = f2fma(xi, sd[1], accP[p][1]);
            accP[p][2] = f2fma(xr, cd[2], accP[p][2]);
            accP[p][2] = f2fma(xi, sd[2], accP[p][2]);
            accP[p][3] = f2fma(xr, cd[3], accP[p][3]);
            accP[p][3] = f2fma(xi, sd[3], accP[p][3]);
        }
    }
    __syncthreads();   // all reads of sXV/sLLP/sXiP/sCyH/sSyH done
#pragma unroll
    for (int p = 0; p < 4; p++) {
        int oA = o0 + 2*p, oB = oA + 1;
        float bA = sLLb[oA], bB = sLLb[oB];
        float2 v0 = f2unpack(accP[p][0]);
        float2 v1 = f2unpack(accP[p][1]);
        float2 v2 = f2unpack(accP[p][2]);
        float2 v3 = f2unpack(accP[p][3]);
        *(float4*)(sXV + oA*128 + tx4) =
            make_float4(v0.x + bA, v1.x + bA, v2.x + bA, v3.x + bA);
        *(float4*)(sXV + oB*128 + tx4) =
            make_float4(v0.y + bB, v1.y + bB, v2.y + bB, v3.y + bB);
    }
    // stage ctx rows (aliases pair-table region)
    for (int i = tid; i < 2048; i += 256) {
        int o = i >> 5, q = i & 31;
        int j = q >> 4, c4 = (q & 15) * 4;
        int cx = j ? cx1 : cx0;
        *(float4*)(sCtx + o*128 + j*64 + c4) =
            *(const float4*)(gctxd + ((size_t)bt*64 + o)*4096 + cx*64 + c4);
    }
    __syncthreads();

    // phase 3: LN stats
    {
        int yy = tid & 127, oh = tid >> 7;
        float s = 0.f, ss = 0.f;
        int ob = oh * 32;
        for (int o = ob; o < ob + 32; o++) {
            float v = sXV[o*128 + yy];
            s += v; ss += v*v;
        }
        sPS[tid] = s; sPQ[tid] = ss;
    }
    __syncthreads();
    if (tid < 128) {
        float s = sPS[tid] + sPS[128 + tid];
        float q = sPQ[tid] + sPQ[128 + tid];
        float mu = s * (1.0f/64.0f);
        float var = q * (1.0f/64.0f) - mu*mu;
        sMu[tid] = mu;
        sRs[tid] = rsqrtf(var + 1e-5f);
    }
    __syncthreads();

    // phase 4 (vectorized): per-thread fixed y-quad; o = j*8 + warp
    int y0 = (tid & 31) * 4;
    float muq[4], rsq[4], wyA[4], wyB[4];
    int cyA[4], cyB[4];
#pragma unroll
    for (int e = 0; e < 4; e++) {
        int y = y0 + e;
        muq[e] = sMu[y]; rsq[e] = sRs[y];
        float cyf = y * 0.5f - 0.25f;
        int iy0 = (int)floorf(cyf);
        float wy1 = cyf - (float)iy0;
        wyB[e] = wy1; wyA[e] = 1.0f - wy1;
        cyA[e] = min(63, max(0, iy0));
        cyB[e] = min(63, max(0, iy0 + 1));
    }
    int warpo = tid >> 5;
    for (int j = 0; j < 8; j++) {
        int o = j*8 + warpo;
        float4 v4 = *(const float4*)(sXV + o*128 + y0);
        float g0_ = sLNg[o], b0_ = sLNb[o];
        const float* cr = sCtx + o*128;
        float r[4] = {v4.x, v4.y, v4.z, v4.w};
#pragma unroll
        for (int e = 0; e < 4; e++) {
            float v = (r[e] - muq[e]) * rsq[e] * g0_ + b0_;
            v = 0.5f * v * (1.0f + erff(v * 0.70710678118654752440f));
            float g = wx0 * (wyA[e] * cr[cyA[e]] + wyB[e] * cr[cyB[e]])
                    + wx1 * (wyA[e] * cr[64 + cyA[e]] + wyB[e] * cr[64 + cyB[e]]);
            r[e] = v + g;
        }
        float4 out4 = make_float4(r[0], r[1], r[2], r[3]);
        *(float4*)(g_X + (((size_t)bt*64 + o)*128 + x)*128 + y0) = out4;
        *(float4*)(sXV + o*128 + y0) = out4;
    }

    // phase 5: fused y-DFT -> g_Yf
    if (write_yf) {
        __syncthreads();
        int warp = tid >> 5, lane = tid & 31;
        const u64* w2 = (const u64*)g_Wfy2;
        int ob = warp * 8;
        u64 acc[8];
#pragma unroll
        for (int r = 0; r < 8; r++) acc[r] = 0ULL;
#pragma unroll 4
        for (int yp = 0; yp < 64; yp++) {
            u64 w = __ldg(w2 + yp*32 + lane);
#pragma unroll
            for (int r = 0; r < 8; r++) {
                u64 v2 = *(const u64*)(sXV + (ob + r)*128 + 2*yp);
                acc[r] = f2fma(v2, w, acc[r]);
            }
        }
#pragma unroll
        for (int r = 0; r < 8; r++) {
            float2 p = f2unpack(acc[r]);
            g_Yf[(((size_t)bt*64 + ob + r)*128 + x)*32 + lane] = p.x + p.y;
        }
    }
}

// ---------------- temporal aggregation + projection ------------------------
__global__ __launch_bounds__(256) void head_kernel(
    const float* __restrict__ Wtw, const float* __restrict__ Wtb,
    const float* __restrict__ Qw,  const float* __restrict__ Qb,
    float* __restrict__ out)
{
    __shared__ float sWt[48], sWtb[4], sQ[192], sQb[3], sQS[3];
    int tid = threadIdx.x;
    if (tid < 48)  sWt[tid]  = Wtw[tid];
    if (tid < 4)   sWtb[tid] = Wtb[tid];
    if (tid < 192) sQ[tid]   = Qw[tid];
    if (tid < 3)   sQb[tid]  = Qb[tid];
    __syncthreads();
    if (tid < 3) {
        float s = 0.f;
        for (int c = 0; c < 64; c++) s += sQ[tid*64 + c];
        sQS[tid] = s;
    }
    __syncthreads();
    int idx = blockIdx.x * 256 + tid;
    int b = idx >> 14, xy = idx & 16383;
    float acc[TOUT][UD] = {};
    for (int c = 0; c < 64; c++) {
        float xv[TIN];
#pragma unroll
        for (int t = 0; t < TIN; t++)
            xv[t] = g_X[(((size_t)(b*TIN + t))*64 + c)*16384 + xy];
        float tt[TOUT];
#pragma unroll
        for (int o = 0; o < TOUT; o++) {
            float s = 0.f;
#pragma unroll
            for (int t = 0; t < TIN; t++) s += sWt[o*TIN + t] * xv[t];
            tt[o] = s;
        }
#pragma unroll
        for (int u = 0; u < UD; u++) {
            float q = sQ[u*64 + c];
#pragma unroll
            for (int o = 0; o < TOUT; o++) acc[o][u] += q * tt[o];
        }
    }
#pragma unroll
    for (int o = 0; o < TOUT; o++)
#pragma unroll
        for (int u = 0; u < UD; u++)
            out[(((size_t)b*TOUT + o)*UD + u)*16384 + xy] =
                acc[o][u] + sWtb[o]*sQS[u] + sQb[u];
}

// ---------------- launcher --------------------------------------------------
extern "C" void kernel_launch(void* const* d_in, const int* in_sizes, int n_in,
                              void* d_out, int out_size)
{
    const float* input = (const float*)d_in[0];
    const float* gctx  = (const float*)d_in[1];
    const float* P_w   = (const float*)d_in[2];
    const float* P_b   = (const float*)d_in[3];
    const float* Q_w   = (const float*)d_in[4];
    const float* Q_b   = (const float*)d_in[5];
    const float* Wt_w  = (const float*)d_in[6];
    const float* Wt_b  = (const float*)d_in[7];
    const float* w1r   = (const float*)d_in[8];
    const float* w1i   = (const float*)d_in[9];
    const float* w2r   = (const float*)d_in[10];
    const float* w2i   = (const float*)d_in[11];
    const float* ll_w  = (const float*)d_in[12];
    const float* ll_b  = (const float*)d_in[13];
    const float* ln_g  = (const float*)d_in[14];
    const float* ln_b  = (const float*)d_in[15];
    float* out = (float*)d_out;

    const int FUSED_SMEM = 18624 * 4;   // 74496 bytes -> 3 blocks/SM
    cudaFuncSetAttribute(fused_tail_kernel,
                         cudaFuncAttributeMaxDynamicSharedMemorySize, FUSED_SMEM);

    init_tables_kernel<<<16, 256>>>();
    dim3 gl(128, NBT);
    lift_fwdy_kernel<<<gl, 256>>>(input, P_w, P_b);

    const size_t SPEC_D = (size_t)64*64*16*16;
    for (int d = 0; d < NDEPTH; d++) {
        fwd_x_kernel<<<1536, 128>>>();
        dim3 g3(2, 12, 16);
        mode_mix_kernel<<<g3, 128>>>(w1r + d*SPEC_D, w1i + d*SPEC_D,
                                     w2r + d*SPEC_D, w2i + d*SPEC_D);
        inv_x_kernel<<<NBT*NC, 256>>>();
        dim3 g5(128, NBT);
        fused_tail_kernel<<<g5, 256, FUSED_SMEM>>>(
            gctx + (size_t)d*NBT*64*4096,
            ll_w + (size_t)d*4096, ll_b + d*64, ln_g + d*64, ln_b + d*64,
            (d < NDEPTH-1) ? 1 : 0);
    }
    head_kernel<<<256, 256>>>(Wt_w, Wt_b, Q_w, Q_b, out);
}

// round 17
// speedup vs baseline: 1.1138x; 1.0651x over previous
#include <cuda_runtime.h>
#include <math.h>

#ifndef M_PI
#define M_PI 3.14159265358979323846
#endif

#define NBT 48
#define NC  64
#define NX  128
#define NY  128
#define NB  4
#define TIN 12
#define TOUT 4
#define UD  3
#define NDEPTH 4

typedef unsigned long long u64;

__device__ __forceinline__ u64 f2fma(u64 a, u64 b, u64 c) {
    u64 r; asm("fma.rn.f32x2 %0,%1,%2,%3;" : "=l"(r) : "l"(a), "l"(b), "l"(c)); return r;
}
__device__ __forceinline__ u64 f2sub(u64 a, u64 b) {
    u64 r; asm("sub.rn.f32x2 %0,%1,%2;" : "=l"(r) : "l"(a), "l"(b)); return r;
}
__device__ __forceinline__ u64 f2pack(float lo, float hi) {
    u64 r; asm("mov.b64 %0,{%1,%2};" : "=l"(r) : "f"(lo), "f"(hi)); return r;
}
__device__ __forceinline__ u64 f2dup(float v) { return f2pack(v, v); }
__device__ __forceinline__ float2 f2unpack(u64 a) {
    float2 r; asm("mov.b64 {%0,%1},%2;" : "=f"(r.x), "=f"(r.y) : "l"(a)); return r;
}
__device__ __forceinline__ u64 f2neg(u64 a) { return a ^ 0x8000000080000000ULL; }

// ---------------- scratch ---------------------------------------------------
__device__ float g_X [NBT*NC*NX*NY];
__device__ float g_Yf[NBT*NC*NX*32];
__device__ float g_Zr[NBT*NC*512];
__device__ float g_Zi[NBT*NC*512];
__device__ float g_Or[NBT*NC*512];
__device__ float g_Oi[NBT*NC*512];
__device__ float g_Xi[NBT*NC*NX*32];
__device__ float g_Wfy2[64*32*2];
__device__ float g_Wfx[128*32*2];
__device__ float g_Wix[32*128*2];
__device__ float g_Cy [16*128];
__device__ float g_Sy [16*128];

// ---------------- table init ------------------------------------------------
__global__ void init_tables_kernel() {
    int tid = blockIdx.x * blockDim.x + threadIdx.x;
    if (tid < 64*32) {
        int yp = tid >> 5, k = tid & 31;
        int kk = k & 15;
        for (int j = 0; j < 2; j++) {
            int y = 2*yp + j;
            double th = (2.0 * M_PI / 128.0) * (double)((kk * y) & 127);
            g_Wfy2[tid*2 + j] = (k < 16) ? (float)cos(th) : (float)(-sin(th));
        }
    }
    if (tid < 128*32) {
        int x = tid >> 5, m = tid & 31;
        int kx = (m < 16) ? m : (96 + m);
        double th = (2.0 * M_PI / 128.0) * (double)((kx * x) & 127);
        g_Wfx[2*tid]   = (float)cos(th);
        g_Wfx[2*tid+1] = (float)(-sin(th));
    }
    if (tid < 32*128) {
        int m = tid >> 7, x = tid & 127;
        int kx = (m < 16) ? m : (96 + m);
        double th = (2.0 * M_PI / 128.0) * (double)((kx * x) & 127);
        g_Wix[2*tid]   = (float)(cos(th) / 128.0);
        g_Wix[2*tid+1] = (float)(sin(th) / 128.0);
    }
    if (tid < 16*128) {
        int k = tid >> 7, y = tid & 127;
        if (k == 0) { g_Cy[tid] = 1.0f/128.0f; g_Sy[tid] = 0.0f; }
        else {
            double th = (2.0 * M_PI / 128.0) * (double)((k * y) & 127);
            g_Cy[tid] = (float)( 2.0 * cos(th) / 128.0);
            g_Sy[tid] = (float)(-2.0 * sin(th) / 128.0);
        }
    }
}

// ---------------- fused lift (3->64) + forward y-DFT -----------------------
__global__ __launch_bounds__(256) void lift_fwdy_kernel(
    const float* __restrict__ in, const float* __restrict__ Pw,
    const float* __restrict__ Pb)
{
    __shared__ float sL[8192];
    __shared__ float sPw[192], sPb[64], sIn[384];
    int tid = threadIdx.x;
    int x = blockIdx.x, bt = blockIdx.y;

    if (tid < 192) sPw[tid] = Pw[tid];
    if (tid < 64)  sPb[tid] = Pb[tid];
    if (tid < 128) {
#pragma unroll
        for (int u = 0; u < 3; u++)
            sIn[u*128 + tid] = in[((size_t)bt*3 + u)*16384 + x*128 + tid];
    }
    __syncthreads();

    for (int i = tid; i < 2048; i += 256) {
        int c = i >> 5, y4 = (i & 31) * 4;
        float b  = sPb[c], w0 = sPw[c*3], w1 = sPw[c*3+1], w2 = sPw[c*3+2];
        float4 r;
        r.x = b + w0*sIn[y4]   + w1*sIn[128+y4]   + w2*sIn[256+y4];
        r.y = b + w0*sIn[y4+1] + w1*sIn[128+y4+1] + w2*sIn[256+y4+1];
        r.z = b + w0*sIn[y4+2] + w1*sIn[128+y4+2] + w2*sIn[256+y4+2];
        r.w = b + w0*sIn[y4+3] + w1*sIn[128+y4+3] + w2*sIn[256+y4+3];
        *(float4*)(sL + c*128 + y4) = r;
        *(float4*)(g_X + (((size_t)bt*64 + c)*128 + x)*128 + y4) = r;
    }
    __syncthreads();

    int warp = tid >> 5, lane = tid & 31;
    const u64* w2 = (const u64*)g_Wfy2;
    int ob = warp * 8;
    u64 acc[8];
#pragma unroll
    for (int r = 0; r < 8; r++) acc[r] = 0ULL;
#pragma unroll 4
    for (int yp = 0; yp < 64; yp++) {
        u64 w = __ldg(w2 + yp*32 + lane);
#pragma unroll
        for (int r = 0; r < 8; r++) {
            u64 v2 = *(const u64*)(sL + (ob + r)*128 + 2*yp);
            acc[r] = f2fma(v2, w, acc[r]);
        }
    }
#pragma unroll
    for (int r = 0; r < 8; r++) {
        float2 p = f2unpack(acc[r]);
        g_Yf[(((size_t)bt*64 + ob + r)*128 + x)*32 + lane] = p.x + p.y;
    }
}

// ---------------- forward DFT over x (R6/R13 version, 128 threads) ---------
__global__ __launch_bounds__(128) void fwd_x_kernel() {
    __shared__ float sY0[4096], sY1[4096];
    int tid = threadIdx.x;
    const float* src = g_Yf + (size_t)blockIdx.x * 8192;
    for (int i = tid; i < 4096; i += 128) { sY0[i] = src[i]; sY1[i] = src[4096 + i]; }
    __syncthreads();
    int m   = tid >> 2;
    int ky0 = (tid & 3) * 4;
    const float2* wtab = (const float2*)g_Wfx;
    u64 rA[2][2], rB[2][2], ii[2][2];
#pragma unroll
    for (int f = 0; f < 2; f++)
#pragma unroll
        for (int p = 0; p < 2; p++) { rA[f][p] = 0ULL; rB[f][p] = 0ULL; ii[f][p] = 0ULL; }
#pragma unroll 2
    for (int x = 0; x < 128; x++) {
        float2 w = __ldg(wtab + x*32 + m);
        u64 wr2 = f2dup(w.x), wi2 = f2dup(w.y);
        u64 a00 = *(const u64*)(sY0 + x*32 + ky0);
        u64 b00 = *(const u64*)(sY0 + x*32 + 16 + ky0);
        u64 a01 = *(const u64*)(sY0 + x*32 + ky0 + 2);
        u64 b01 = *(const u64*)(sY0 + x*32 + 18 + ky0);
        u64 a10 = *(const u64*)(sY1 + x*32 + ky0);
        u64 b10 = *(const u64*)(sY1 + x*32 + 16 + ky0);
        u64 a11 = *(const u64*)(sY1 + x*32 + ky0 + 2);
        u64 b11 = *(const u64*)(sY1 + x*32 + 18 + ky0);
        rA[0][0] = f2fma(a00, wr2, rA[0][0]);  rB[0][0] = f2fma(b00, wi2, rB[0][0]);
        ii[0][0] = f2fma(a00, wi2, ii[0][0]);  ii[0][0] = f2fma(b00, wr2, ii[0][0]);
        rA[0][1] = f2fma(a01, wr2, rA[0][1]);  rB[0][1] = f2fma(b01, wi2, rB[0][1]);
        ii[0][1] = f2fma(a01, wi2, ii[0][1]);  ii[0][1] = f2fma(b01, wr2, ii[0][1]);
        rA[1][0] = f2fma(a10, wr2, rA[1][0]);  rB[1][0] = f2fma(b10, wi2, rB[1][0]);
        ii[1][0] = f2fma(a10, wi2, ii[1][0]);  ii[1][0] = f2fma(b10, wr2, ii[1][0]);
        rA[1][1] = f2fma(a11, wr2, rA[1][1]);  rB[1][1] = f2fma(b11, wi2, rB[1][1]);
        ii[1][1] = f2fma(a11, wi2, ii[1][1]);  ii[1][1] = f2fma(b11, wr2, ii[1][1]);
    }
#pragma unroll
    for (int f = 0; f < 2; f++) {
        size_t base = ((size_t)(blockIdx.x*2 + f))*512 + m*16 + ky0;
        *(u64*)(g_Zr + base)     = f2sub(rA[f][0], rB[f][0]);
        *(u64*)(g_Zr + base + 2) = f2sub(rA[f][1], rB[f][1]);
        *(u64*)(g_Zi + base)     = ii[f][0];
        *(u64*)(g_Zi + base + 2) = ii[f][1];
    }
}

// ---------------- per-mode channel mix (R9 4bt x 4o version) ---------------
__global__ __launch_bounds__(128) void mode_mix_kernel(
    const float* __restrict__ w1r, const float* __restrict__ w1i,
    const float* __restrict__ w2r, const float* __restrict__ w2i)
{
    int mp    = blockIdx.x * 128 + threadIdx.x;
    int mode0 = mp * 2;
    int half  = mode0 >> 8;
    int ml    = mode0 & 255;
    const float* Wr = half ? w2r : w1r;
    const float* Wi = half ? w2i : w1i;
    int bt0 = blockIdx.y * 4, o0 = blockIdx.z * 4;
    u64 aR[4][4], aI[4][4];
#pragma unroll
    for (int b = 0; b < 4; b++)
#pragma unroll
        for (int o = 0; o < 4; o++) { aR[b][o] = 0ULL; aI[b][o] = 0ULL; }

    for (int i = 0; i < 64; i++) {
        u64 zr[4], zi[4];
#pragma unroll
        for (int b = 0; b < 4; b++) {
            size_t zb = ((size_t)(bt0 + b)*64 + i)*512 + mode0;
            zr[b] = *(const u64*)(g_Zr + zb);
            zi[b] = *(const u64*)(g_Zi + zb);
        }
#pragma unroll
        for (int o = 0; o < 4; o++) {
            size_t wb = ((size_t)i*64 + (o0 + o))*256 + ml;
            u64 wr2  = *(const u64*)(Wr + wb);
            u64 wi2  = *(const u64*)(Wi + wb);
            u64 wi2n = f2neg(wi2);
#pragma unroll
            for (int b = 0; b < 4; b++) {
                aR[b][o] = f2fma(zr[b], wr2,  aR[b][o]);
                aR[b][o] = f2fma(zi[b], wi2n, aR[b][o]);
                aI[b][o] = f2fma(zr[b], wi2,  aI[b][o]);
                aI[b][o] = f2fma(zi[b], wr2,  aI[b][o]);
            }
        }
    }
#pragma unroll
    for (int b = 0; b < 4; b++)
#pragma unroll
        for (int o = 0; o < 4; o++) {
            size_t ob = ((size_t)(bt0 + b)*64 + (o0 + o))*512 + mode0;
            *(u64*)(g_Or + ob) = aR[b][o];
            *(u64*)(g_Oi + ob) = aI[b][o];
        }
}

// ---------------- inverse DFT over x ---------------------------------------
__global__ __launch_bounds__(256) void inv_x_kernel() {
    __shared__ float sOr[512], sOi[512];
    int tid = threadIdx.x;
    const float* srcr = g_Or + (size_t)blockIdx.x * 512;
    const float* srci = g_Oi + (size_t)blockIdx.x * 512;
    for (int i = tid; i < 512; i += 256) { sOr[i] = srcr[i]; sOi[i] = srci[i]; }
    __syncthreads();
    int x  = tid >> 1;
    int kb = (tid & 1) * 8;
    u64 arA[4], arB[4], ai[4];
#pragma unroll
    for (int j = 0; j < 4; j++) { arA[j] = 0ULL; arB[j] = 0ULL; ai[j] = 0ULL; }
#pragma unroll 4
    for (int m = 0; m < 32; m++) {
        float2 w = *(const float2*)(g_Wix + (m*128 + x)*2);
        u64 wr2 = f2dup(w.x), wi2 = f2dup(w.y);
#pragma unroll
        for (int j = 0; j < 4; j++) {
            u64 pr = *(const u64*)(sOr + m*16 + kb + 2*j);
            u64 pi = *(const u64*)(sOi + m*16 + kb + 2*j);
            arA[j] = f2fma(pr, wr2, arA[j]);
            arB[j] = f2fma(pi, wi2, arB[j]);
            ai[j]  = f2fma(pr, wi2, ai[j]);
            ai[j]  = f2fma(pi, wr2, ai[j]);
        }
    }
    float* dst = g_Xi + ((size_t)blockIdx.x * 128 + x) * 32;
#pragma unroll
    for (int j = 0; j < 4; j++) {
        *(u64*)(dst + kb + 2*j)      = f2sub(arA[j], arB[j]);
        *(u64*)(dst + 16 + kb + 2*j) = ai[j];
    }
}

// ---------------- fused tail v7 (R16, unchanged) ---------------------------
__global__ __launch_bounds__(256, 3) void fused_tail_kernel(
    const float* __restrict__ gctxd,
    const float* __restrict__ llw,
    const float* __restrict__ llb,
    const float* __restrict__ lng, const float* __restrict__ lnb,
    int write_yf)
{
    extern __shared__ float sm[];
    float* sXV  = sm;
    u64*   sLLP = (u64*)(sm + 8192);    // [c*33 + p], p = o/2
    u64*   sXiP = (u64*)(sm + 12416);   // [k*33 + p]
    float* sCtx = sm + 8192;            // alias after phase 2
    float* sCyH = sm + 16384;
    float* sSyH = sm + 17408;
    float* sPS  = sm + 16384;           // alias after phase 2
    float* sPQ  = sm + 16640;
    float* sMu  = sm + 16896;
    float* sRs  = sm + 17024;
    float* sLNg = sm + 18432;
    float* sLNb = sm + 18496;
    float* sLLb = sm + 18560;

    int tid = threadIdx.x;
    int x   = blockIdx.x;
    int bt  = blockIdx.y;

    float cxf = x * 0.5f - 0.25f;
    int ix0 = (int)floorf(cxf);
    float wx1 = cxf - (float)ix0, wx0 = 1.0f - wx1;
    int cx0 = min(63, max(0, ix0));
    int cx1 = min(63, max(0, ix0 + 1));

    // phase 1: loads
    for (int i = tid; i < 2048; i += 256) {
        int c = i >> 5, y4 = (i & 31) * 4;
        *(float4*)(sXV + c*128 + y4) =
            *(const float4*)(g_X + (((size_t)bt*64 + c)*128 + x)*128 + y4);
    }
    for (int i = tid; i < 2048; i += 256) {
        int c = i & 63, pp = i >> 6;
        sLLP[c*33 + pp] = f2pack(llw[(2*pp)*64 + c], llw[(2*pp+1)*64 + c]);
    }
    {
        const float* xb = g_Xi + (((size_t)bt*64)*128 + x)*32;
        for (int i = tid; i < 1024; i += 256) {
            int k = i & 31, pp = i >> 5;
            float lo = xb[(size_t)(2*pp)*4096 + k];
            float hi = xb[(size_t)(2*pp+1)*4096 + k];
            sXiP[k*33 + pp] = f2pack(lo, hi);
        }
    }
    for (int i = tid; i < 1024; i += 256) {
        int k = i >> 6, yy = i & 63;
        sCyH[i] = g_Cy[k*128 + yy];
        sSyH[i] = g_Sy[k*128 + yy];
    }
    if (tid < 64) { sLNg[tid] = lng[tid]; sLNb[tid] = lnb[tid]; sLLb[tid] = llb[tid]; }
    __syncthreads();

    // phase 2: V[o][y] = LL @ X + inv-y(Xi) ; pairs over o
    int o0  = (tid >> 5) * 8;
    int p0  = (tid >> 5) * 4;
    int tx4 = (tid & 31) * 4;
    int yh  = tx4 & 63;
    u64 sgn = (tx4 >= 64) ? 0x8000000080000000ULL : 0ULL;
    u64 accP[4][4];
#pragma unroll
    for (int p = 0; p < 4; p++)
#pragma unroll
        for (int e = 0; e < 4; e++) accP[p][e] = 0ULL;

#pragma unroll 2
    for (int c = 0; c < 64; c++) {
        float4 xq = *(const float4*)(sXV + c*128 + tx4);
        u64 xd0 = f2dup(xq.x), xd1 = f2dup(xq.y), xd2 = f2dup(xq.z), xd3 = f2dup(xq.w);
        const u64* wrow = sLLP + c*33 + p0;
#pragma unroll
        for (int p = 0; p < 4; p++) {
            u64 wp = wrow[p];
            accP[p][0] = f2fma(xd0, wp, accP[p][0]);
            accP[p][1] = f2fma(xd1, wp, accP[p][1]);
            accP[p][2] = f2fma(xd2, wp, accP[p][2]);
            accP[p][3] = f2fma(xd3, wp, accP[p][3]);
        }
    }
#pragma unroll
    for (int ky = 0; ky < 16; ky++) {
        float4 cq = *(const float4*)(sCyH + ky*64 + yh);
        float4 sq = *(const float4*)(sSyH + ky*64 + yh);
        u64 cd[4] = {f2dup(cq.x), f2dup(cq.y), f2dup(cq.z), f2dup(cq.w)};
        u64 sd[4] = {f2dup(sq.x), f2dup(sq.y), f2dup(sq.z), f2dup(sq.w)};
        if (ky & 1) {
#pragma unroll
            for (int e = 0; e < 4; e++) { cd[e] ^= sgn; sd[e] ^= sgn; }
        }
        const u64* xrrow = sXiP + ky*33 + p0;
        const u64* xirow = sXiP + (16 + ky)*33 + p0;
#pragma unroll
        for (int p = 0; p < 4; p++) {
            u64 xr = xrrow[p];
            u64 xi = xirow[p];
            accP[p][0] = f2fma(xr, cd[0], accP[p][0]);
            accP[p][0] = f2fma(xi, sd[0], accP[p][0]);
            accP[p][1] = f2fma(xr, cd[1], accP[p][1]);
            accP[p][1] = f2fma(xi, sd[1], accP[p][1]);
            accP[p][2] = f2fma(xr, cd[2], accP[p][2]);
            accP[p][2] = f2fma(xi, sd[2], accP[p][2]);
            accP[p][3] = f2fma(xr, cd[3], accP[p][3]);
            accP[p][3] = f2fma(xi, sd[3], accP[p][3]);
        }
    }
    __syncthreads();
#pragma unroll
    for (int p = 0; p < 4; p++) {
        int oA = o0 + 2*p, oB = oA + 1;
        float bA = sLLb[oA], bB = sLLb[oB];
        float2 v0 = f2unpack(accP[p][0]);
        float2 v1 = f2unpack(accP[p][1]);
        float2 v2 = f2unpack(accP[p][2]);
        float2 v3 = f2unpack(accP[p][3]);
        *(float4*)(sXV + oA*128 + tx4) =
            make_float4(v0.x + bA, v1.x + bA, v2.x + bA, v3.x + bA);
        *(float4*)(sXV + oB*128 + tx4) =
            make_float4(v0.y + bB, v1.y + bB, v2.y + bB, v3.y + bB);
    }
    for (int i = tid; i < 2048; i += 256) {
        int o = i >> 5, q = i & 31;
        int j = q >> 4, c4 = (q & 15) * 4;
        int cx = j ? cx1 : cx0;
        *(float4*)(sCtx + o*128 + j*64 + c4) =
            *(const float4*)(gctxd + ((size_t)bt*64 + o)*4096 + cx*64 + c4);
    }
    __syncthreads();

    // phase 3: LN stats
    {
        int yy = tid & 127, oh = tid >> 7;
        float s = 0.f, ss = 0.f;
        int ob = oh * 32;
        for (int o = ob; o < ob + 32; o++) {
            float v = sXV[o*128 + yy];
            s += v; ss += v*v;
        }
        sPS[tid] = s; sPQ[tid] = ss;
    }
    __syncthreads();
    if (tid < 128) {
        float s = sPS[tid] + sPS[128 + tid];
        float q = sPQ[tid] + sPQ[128 + tid];
        float mu = s * (1.0f/64.0f);
        float var = q * (1.0f/64.0f) - mu*mu;
        sMu[tid] = mu;
        sRs[tid] = rsqrtf(var + 1e-5f);
    }
    __syncthreads();

    // phase 4 (vectorized): per-thread fixed y-quad; o = j*8 + warp
    int y0 = (tid & 31) * 4;
    float muq[4], rsq[4], wyA[4], wyB[4];
    int cyA[4], cyB[4];
#pragma unroll
    for (int e = 0; e < 4; e++) {
        int y = y0 + e;
        muq[e] = sMu[y]; rsq[e] = sRs[y];
        float cyf = y * 0.5f - 0.25f;
        int iy0 = (int)floorf(cyf);
        float wy1 = cyf - (float)iy0;
        wyB[e] = wy1; wyA[e] = 1.0f - wy1;
        cyA[e] = min(63, max(0, iy0));
        cyB[e] = min(63, max(0, iy0 + 1));
    }
    int warpo = tid >> 5;
    for (int j = 0; j < 8; j++) {
        int o = j*8 + warpo;
        float4 v4 = *(const float4*)(sXV + o*128 + y0);
        float g0_ = sLNg[o], b0_ = sLNb[o];
        const float* cr = sCtx + o*128;
        float r[4] = {v4.x, v4.y, v4.z, v4.w};
#pragma unroll
        for (int e = 0; e < 4; e++) {
            float v = (r[e] - muq[e]) * rsq[e] * g0_ + b0_;
            v = 0.5f * v * (1.0f + erff(v * 0.70710678118654752440f));
            float g = wx0 * (wyA[e] * cr[cyA[e]] + wyB[e] * cr[cyB[e]])
                    + wx1 * (wyA[e] * cr[64 + cyA[e]] + wyB[e] * cr[64 + cyB[e]]);
            r[e] = v + g;
        }
        float4 out4 = make_float4(r[0], r[1], r[2], r[3]);
        *(float4*)(g_X + (((size_t)bt*64 + o)*128 + x)*128 + y0) = out4;
        *(float4*)(sXV + o*128 + y0) = out4;
    }

    // phase 5: fused y-DFT -> g_Yf
    if (write_yf) {
        __syncthreads();
        int warp = tid >> 5, lane = tid & 31;
        const u64* w2 = (const u64*)g_Wfy2;
        int ob = warp * 8;
        u64 acc[8];
#pragma unroll
        for (int r = 0; r < 8; r++) acc[r] = 0ULL;
#pragma unroll 4
        for (int yp = 0; yp < 64; yp++) {
            u64 w = __ldg(w2 + yp*32 + lane);
#pragma unroll
            for (int r = 0; r < 8; r++) {
                u64 v2 = *(const u64*)(sXV + (ob + r)*128 + 2*yp);
                acc[r] = f2fma(v2, w, acc[r]);
            }
        }
#pragma unroll
        for (int r = 0; r < 8; r++) {
            float2 p = f2unpack(acc[r]);
            g_Yf[(((size_t)bt*64 + ob + r)*128 + x)*32 + lane] = p.x + p.y;
        }
    }
}

// ---------------- head v2: c-split x4, grid 1024 ---------------------------
// block = 256 threads = 64 outputs x 4 c-chunks; smem reduce
__global__ __launch_bounds__(256) void head_kernel(
    const float* __restrict__ Wtw, const float* __restrict__ Wtb,
    const float* __restrict__ Qw,  const float* __restrict__ Qb,
    float* __restrict__ out)
{
    __shared__ float sWt[48], sWtb[4], sQ[192], sQb[3], sQS[3];
    __shared__ float sRed[256*12];
    int tid = threadIdx.x;
    if (tid < 48)  sWt[tid]  = Wtw[tid];
    if (tid < 4)   sWtb[tid] = Wtb[tid];
    if (tid < 192) sQ[tid]   = Qw[tid];
    if (tid < 3)   sQb[tid]  = Qb[tid];
    __syncthreads();
    if (tid < 3) {
        float s = 0.f;
        for (int c = 0; c < 64; c++) s += sQ[tid*64 + c];
        sQS[tid] = s;
    }
    __syncthreads();

    int idx = blockIdx.x * 64 + (tid & 63);   // over 4*16384 outputs
    int b = idx >> 14, xy = idx & 16383;
    int c0 = (tid >> 6) * 16;                 // c-chunk base

    float acc[TOUT][UD] = {};
    for (int cc = 0; cc < 16; cc++) {
        int c = c0 + cc;
        float xv[TIN];
#pragma unroll
        for (int t = 0; t < TIN; t++)
            xv[t] = g_X[(((size_t)(b*TIN + t))*64 + c)*16384 + xy];
        float tt[TOUT];
#pragma unroll
        for (int o = 0; o < TOUT; o++) {
            float s = 0.f;
#pragma unroll
            for (int t = 0; t < TIN; t++) s += sWt[o*TIN + t] * xv[t];
            tt[o] = s;
        }
#pragma unroll
        for (int u = 0; u < UD; u++) {
            float q = sQ[u*64 + c];
#pragma unroll
            for (int o = 0; o < TOUT; o++) acc[o][u] += q * tt[o];
        }
    }
#pragma unroll
    for (int o = 0; o < TOUT; o++)
#pragma unroll
        for (int u = 0; u < UD; u++)
            sRed[tid*12 + o*UD + u] = acc[o][u];
    __syncthreads();
    if (tid < 64) {
#pragma unroll
        for (int o = 0; o < TOUT; o++)
#pragma unroll
            for (int u = 0; u < UD; u++) {
                int j = o*UD + u;
                float s = sRed[tid*12 + j] + sRed[(tid+64)*12 + j]
                        + sRed[(tid+128)*12 + j] + sRed[(tid+192)*12 + j];
                out[(((size_t)b*TOUT + o)*UD + u)*16384 + xy] =
                    s + sWtb[o]*sQS[u] + sQb[u];
            }
    }
}

// ---------------- launcher --------------------------------------------------
extern "C" void kernel_launch(void* const* d_in, const int* in_sizes, int n_in,
                              void* d_out, int out_size)
{
    const float* input = (const float*)d_in[0];
    const float* gctx  = (const float*)d_in[1];
    const float* P_w   = (const float*)d_in[2];
    const float* P_b   = (const float*)d_in[3];
    const float* Q_w   = (const float*)d_in[4];
    const float* Q_b   = (const float*)d_in[5];
    const float* Wt_w  = (const float*)d_in[6];
    const float* Wt_b  = (const float*)d_in[7];
    const float* w1r   = (const float*)d_in[8];
    const float* w1i   = (const float*)d_in[9];
    const float* w2r   = (const float*)d_in[10];
    const float* w2i   = (const float*)d_in[11];
    const float* ll_w  = (const float*)d_in[12];
    const float* ll_b  = (const float*)d_in[13];
    const float* ln_g  = (const float*)d_in[14];
    const float* ln_b  = (const float*)d_in[15];
    float* out = (float*)d_out;

    const int FUSED_SMEM = 18624 * 4;   // 74496 bytes -> 3 blocks/SM
    cudaFuncSetAttribute(fused_tail_kernel,
                         cudaFuncAttributeMaxDynamicSharedMemorySize, FUSED_SMEM);

    init_tables_kernel<<<16, 256>>>();
    dim3 gl(128, NBT);
    lift_fwdy_kernel<<<gl, 256>>>(input, P_w, P_b);

    const size_t SPEC_D = (size_t)64*64*16*16;
    for (int d = 0; d < NDEPTH; d++) {
        fwd_x_kernel<<<1536, 128>>>();
        dim3 g3(2, 12, 16);
        mode_mix_kernel<<<g3, 128>>>(w1r + d*SPEC_D, w1i + d*SPEC_D,
                                     w2r + d*SPEC_D, w2i + d*SPEC_D);
        inv_x_kernel<<<NBT*NC, 256>>>();
        dim3 g5(128, NBT);
        fused_tail_kernel<<<g5, 256, FUSED_SMEM>>>(
            gctx + (size_t)d*NBT*64*4096,
            ll_w + (size_t)d*4096, ll_b + d*64, ln_g + d*64, ln_b + d*64,
            (d < NDEPTH-1) ? 1 : 0);
    }
    head_kernel<<<1024, 256>>>(Wt_w, Wt_b, Q_w, Q_b, out);
}